// round 13
// baseline (speedup 1.0000x reference)
#include <cuda_runtime.h>
#include <cstdint>
#include <cstddef>

#define B_   1024
#define NT   128
#define NY   128
#define C_   512
#define EOS_ 1

#define NCHUNK 4
#define BCHUNK (B_ / NCHUNK)          // 256 batches per chunk

// Compact gathered coefficients: G[b][t][{pC,pI}][j], t slot 127 = pad.
// 128 MiB scratch (device .bss).
__device__ float4 g_G4[(size_t)B_ * NT * 2 * (NY / 4)];

// Padded SMEM row stride (floats): multiple of 4 (16B cp.async), %32==4.
#define RSTRIDE 516

// ---------------------------------------------------------------------------
// Phase 1 (R10-proven best): gather/transpose. CTA = one (batch, array):
//   pair = blockIdx.x + goff;  b = pair>>1, arr = pair&1.
// 16-row groups, double-buffered cp.async.cg, skipping 16B chunks no target
// touches. Epilogue: one thread owns (t, j-quad) -> 4 LDS + 1 STG.128.
// ---------------------------------------------------------------------------
__global__ __launch_bounds__(256, 3) void gather_kernel(
    const float* __restrict__ pred, const float* __restrict__ R,
    const float* __restrict__ I, const int* __restrict__ target, int goff) {
  extern __shared__ float stage[];  // [2][16 * RSTRIDE]
  __shared__ int tgt_s[NT];
  __shared__ float rS[NY];
  __shared__ unsigned mask_s[4];    // 128-bit mask over 16B chunks

  const int pair = blockIdx.x + goff;
  const int b   = pair >> 1;
  const int arr = pair & 1;
  const int tid = threadIdx.x;
  float* g_G = (float*)g_G4;

  if (tid < 4) mask_s[tid] = 0u;
  if (tid < NT) tgt_s[tid] = target[b * NT + tid];
  if (tid < NY) {
    const int base = (b * NY + tid) * 3;
    rS[tid] = arr ? ((tid == NY - 1) ? 1.0f : R[base + 1]) : R[base];
  }
  __syncthreads();
  if (tid < NT - 1) {  // only t=0..126 are gathered
    const int cbit = tgt_s[tid] >> 2;
    atomicOr(&mask_s[cbit >> 5], 1u << (cbit & 31));
  }
  __syncthreads();

  const int cc = tid & 127;  // 16B chunk index
  const unsigned on = (mask_s[cc >> 5] >> (cc & 31)) & 1u;
  const int rbase = tid >> 7;  // 0 or 1
  const float* __restrict__ src_arr = arr ? I : pred;

  auto issue = [&](int g) {
    const int r0 = g * 16;
    const float* src = src_arr + ((size_t)b * NY + r0) * C_ + cc * 4;
    float* buf = stage + (g & 1) * (16 * RSTRIDE) + cc * 4;
#pragma unroll
    for (int p = 0; p < 8; ++p) {
      const int r = rbase + 2 * p;
      unsigned sa = (unsigned)__cvta_generic_to_shared(buf + r * RSTRIDE);
      const float* gp = src + (size_t)r * C_;
      asm volatile(
          "{ .reg .pred p0; setp.ne.u32 p0, %0, 0;"
          " @p0 cp.async.cg.shared.global [%1], [%2], 16; }"
          :: "r"(on), "r"(sa), "l"(gp) : "memory");
    }
    asm volatile("cp.async.commit_group;" ::: "memory");
  };

  issue(0);
  issue(1);

  // Epilogue mapping: jq = quad within 16-row group (0..3), tq = t base.
  const int jq = tid & 3;
  const int tq = tid >> 2;  // 0..63; t = tq + 64*p
  const int tt0 = (tq < NT - 1) ? tgt_s[tq] : 0;
  const int tt1 = (tq + 64 < NT - 1) ? tgt_s[tq + 64] : 0;

  for (int g = 0; g < 8; ++g) {
    if (g == 7) asm volatile("cp.async.wait_group 0;" ::: "memory");
    else        asm volatile("cp.async.wait_group 1;" ::: "memory");
    __syncthreads();

    const int r0 = g * 16;
    const float s0 = rS[r0 + jq * 4 + 0];
    const float s1 = rS[r0 + jq * 4 + 1];
    const float s2 = rS[r0 + jq * 4 + 2];
    const float s3 = rS[r0 + jq * 4 + 3];
    const float* buf = stage + (g & 1) * (16 * RSTRIDE) + (jq * 4) * RSTRIDE;

    {  // t = tq (always < 127 since tq <= 63)
      const float* col = buf + tt0;
      float4 v;
      v.x = col[0 * RSTRIDE] * s0;
      v.y = col[1 * RSTRIDE] * s1;
      v.z = col[2 * RSTRIDE] * s2;
      v.w = col[3 * RSTRIDE] * s3;
      *(float4*)&g_G[(((size_t)b * NT + tq) * 2 + arr) * NY + r0 + jq * 4] = v;
    }
    if (tq + 64 < NT - 1) {  // t = tq + 64 (skip t = 127)
      const float* col = buf + tt1;
      float4 v;
      v.x = col[0 * RSTRIDE] * s0;
      v.y = col[1 * RSTRIDE] * s1;
      v.z = col[2 * RSTRIDE] * s2;
      v.w = col[3 * RSTRIDE] * s3;
      *(float4*)&g_G[(((size_t)b * NT + tq + 64) * 2 + arr) * NY + r0 + jq * 4] = v;
    }
    __syncthreads();
    if (g + 2 < 8) issue(g + 2);
  }
}

// ---------------------------------------------------------------------------
// Phase 2 (R10-proven, regs 31): warp per batch (b = boff + 4*bid + w);
// lane l owns j = 4l..4l+3. Affine (A,D) warp scan, PF=14 cp.async ring.
// ---------------------------------------------------------------------------
#define PF 14

__global__ __launch_bounds__(128) void scan_kernel(
    const float* __restrict__ R, const int* __restrict__ target,
    float* __restrict__ out, int boff) {
  extern __shared__ float ring[];  // [4 warps][16 slots][256 floats] = 64 KB
  const int l = threadIdx.x & 31;
  const int w = threadIdx.x >> 5;
  const int b = boff + blockIdx.x * 4 + w;
  const unsigned FULL = 0xffffffffu;

  float* wring = ring + w * (16 * 256);
  const float* __restrict__ gG = (const float*)g_G4;
  const size_t gbase = (size_t)b * NT * 256;

  auto issue_row = [&](int r) {
    const float* s1 = gG + gbase + (size_t)r * 256 + l * 4;
    float* d1 = wring + (r & 15) * 256 + l * 4;
    unsigned da = (unsigned)__cvta_generic_to_shared(d1);
    asm volatile(
        "cp.async.cg.shared.global [%0], [%1], 16;\n"
        "cp.async.cg.shared.global [%2], [%3], 16;\n"
        :: "r"(da), "l"(s1), "r"(da + 512), "l"(s1 + 128) : "memory");
    asm volatile("cp.async.commit_group;" ::: "memory");
  };

#pragma unroll
  for (int k = 0; k < PF; ++k) issue_row(k);

  unsigned em[4];
#pragma unroll
  for (int m = 0; m < 4; ++m) {
    const int tg = target[b * NT + l + 32 * m];
    em[m] = __ballot_sync(FULL, tg == EOS_);
  }

  float r2[4];
#pragma unroll
  for (int k = 0; k < 4; ++k)
    r2[k] = R[((size_t)b * NY + 4 * l + k) * 3 + 2];
  const float r2p = __shfl_up_sync(FULL, r2[3], 1);
  const float dsh0 = (l == 0) ? 1.0f : r2p;

  const bool eos0 = em[0] & 1u;
  const float m0v = (l == 0) ? 1.0f : (eos0 ? 1.0f : r2[0]);
  const float m1v = eos0 ? 1.0f : r2[1];
  const float m2v = eos0 ? 1.0f : r2[2];
  const float m3v = eos0 ? 1.0f : r2[3];
  const float P0 = m0v, P1 = P0 * m1v, P2 = P1 * m2v, P3 = P2 * m3v;
  float Pw = P3;
#pragma unroll
  for (int off = 1; off < 32; off <<= 1) {
    const float Po = __shfl_up_sync(FULL, Pw, off);
    if (l >= off) Pw *= Po;
  }
  float pin = __shfl_up_sync(FULL, Pw, 1);
  if (l == 0) pin = 1.0f;
  float row0 = P0 * pin, row1 = P1 * pin, row2 = P2 * pin, row3 = P3 * pin;

  asm volatile("cp.async.wait_group 13;" ::: "memory");  // row 0 ready
  float4 cpc = *(const float4*)(wring + 0 * 256 + l * 4);
  float4 cpi = *(const float4*)(wring + 0 * 256 + 128 + l * 4);

  for (int i = 0; i < NT - 1; ++i) {
    const int rf = i + PF;
    if (rf <= 127) issue_row(rf);
    else asm volatile("cp.async.commit_group;" ::: "memory");

    asm volatile("cp.async.wait_group 13;" ::: "memory");
    const int slot = (i + 1) & 15;
    const float4 npc = *(const float4*)(wring + slot * 256 + l * 4);
    const float4 npi = *(const float4*)(wring + slot * 256 + 128 + l * 4);

    const int ts = i + 1;
    const unsigned ew = (ts & 64) ? ((ts & 32) ? em[3] : em[2])
                                  : ((ts & 32) ? em[1] : em[0]);
    const bool eos = (ew >> (ts & 31)) & 1u;
    const float d0 = eos ? 1.0f : dsh0;
    const float d1 = eos ? 1.0f : r2[0];
    const float d2 = eos ? 1.0f : r2[1];
    const float d3 = eos ? 1.0f : r2[2];

    // a_full[j] = row[j-1]*pC[j-1] + row[j]*pI[j]   (j=0: row[0]*pI[0])
    const float q3 = row3 * cpc.w;
    float qp = __shfl_up_sync(FULL, q3, 1);
    if (l == 0) qp = 0.0f;
    const float a0 = fmaf(row0, cpi.x, qp);
    const float a1 = fmaf(row1, cpi.y, row0 * cpc.x);
    const float a2 = fmaf(row2, cpi.z, row1 * cpc.y);
    const float a3 = fmaf(row3, cpi.w, row2 * cpc.z);

    const float A0 = a0, D0 = d0;
    const float A1 = fmaf(d1, A0, a1), D1 = d1 * D0;
    const float A2 = fmaf(d2, A1, a2), D2 = d2 * D1;
    const float A3 = fmaf(d3, A2, a3), D3 = d3 * D2;

    float As = A3, Ds = D3;
#pragma unroll
    for (int off = 1; off < 32; off <<= 1) {
      const float Ao = __shfl_up_sync(FULL, As, off);
      const float Do = __shfl_up_sync(FULL, Ds, off);
      if (l >= off) { As = fmaf(Ds, Ao, As); Ds *= Do; }
    }
    float xin = __shfl_up_sync(FULL, As, 1);
    if (l == 0) xin = 0.0f;

    row0 = fmaf(D0, xin, A0);
    row1 = fmaf(D1, xin, A1);
    row2 = fmaf(D2, xin, A2);
    row3 = As;

    cpc = npc; cpi = npi;
  }

  if (l == 31) out[b] = row3;
}

// ---------------------------------------------------------------------------
// Chunked pipeline: gather chunks serialize on the caller's (capture) stream;
// each scan chunk runs on a second stream gated by an event recorded after
// its gather chunk -> scan_k overlaps gather_{k+1} as independent graph
// branches. Falls back to fully serialized chunks if stream setup fails.
// ---------------------------------------------------------------------------
extern "C" void kernel_launch(void* const* d_in, const int* in_sizes, int n_in,
                              void* d_out, int out_size) {
  const float* pred   = (const float*)d_in[0];
  const float* R      = (const float*)d_in[1];
  const float* I      = (const float*)d_in[2];
  const int*   target = (const int*)d_in[3];
  float* out = (float*)d_out;

  const int smem_g = 2 * 16 * RSTRIDE * (int)sizeof(float);  // 66048 B
  cudaFuncSetAttribute(gather_kernel,
                       cudaFuncAttributeMaxDynamicSharedMemorySize, smem_g);
  const int smem_s = 4 * 16 * 256 * (int)sizeof(float);      // 65536 B
  cudaFuncSetAttribute(scan_kernel,
                       cudaFuncAttributeMaxDynamicSharedMemorySize, smem_s);

  cudaStream_t s2 = nullptr;
  cudaEvent_t evG[NCHUNK] = {}, evJoin = nullptr;
  bool forked = (cudaStreamCreateWithFlags(&s2, cudaStreamNonBlocking)
                 == cudaSuccess);
  if (forked) {
    for (int k = 0; k < NCHUNK && forked; ++k)
      forked = (cudaEventCreateWithFlags(&evG[k], cudaEventDisableTiming)
                == cudaSuccess);
    if (forked)
      forked = (cudaEventCreateWithFlags(&evJoin, cudaEventDisableTiming)
                == cudaSuccess);
  }

  if (forked) {
    for (int k = 0; k < NCHUNK; ++k) {
      gather_kernel<<<BCHUNK * 2, 256, smem_g, 0>>>(pred, R, I, target,
                                                    k * BCHUNK * 2);
      cudaEventRecord(evG[k], 0);
      cudaStreamWaitEvent(s2, evG[k], 0);
      scan_kernel<<<BCHUNK / 4, 128, smem_s, s2>>>(R, target, out,
                                                   k * BCHUNK);
    }
    cudaEventRecord(evJoin, s2);
    cudaStreamWaitEvent(0, evJoin, 0);
  } else {
    // Serialized fallback (identical work, default stream).
    for (int k = 0; k < NCHUNK; ++k) {
      gather_kernel<<<BCHUNK * 2, 256, smem_g>>>(pred, R, I, target,
                                                 k * BCHUNK * 2);
      scan_kernel<<<BCHUNK / 4, 128, smem_s>>>(R, target, out, k * BCHUNK);
    }
  }

  if (evJoin) cudaEventDestroy(evJoin);
  for (int k = 0; k < NCHUNK; ++k)
    if (evG[k]) cudaEventDestroy(evG[k]);
  if (s2) cudaStreamDestroy(s2);
}

// round 14
// speedup vs baseline: 1.2151x; 1.2151x over previous
#include <cuda_runtime.h>
#include <cstdint>
#include <cstddef>

#define B_   1024
#define NT   128
#define NY   128
#define C_   512
#define EOS_ 1

// Compact gathered coefficients: G[b][t][{pC,pI}][j], t slot 127 = pad.
// 128 MiB scratch (device .bss).
__device__ float4 g_G4[(size_t)B_ * NT * 2 * (NY / 4)];

// Padded SMEM row stride (floats): multiple of 4 (16B cp.async), %32==4.
#define RSTRIDE 516

// ---------------------------------------------------------------------------
// Phase 1 (R10-proven): gather/transpose. CTA = one (batch, array):
//   blockIdx.x = b*2 + arr   (arr 0 = pred -> pC, arr 1 = I -> pI)
// 16-row groups, double-buffered cp.async.cg, skipping 16B chunks no target
// touches. L2 policy: streaming reads evict_first (single-use), G stores
// evict_last (keep resident for the scan kernel). Epilogue: one thread owns
// (t, j-quad) -> 4 LDS + 1 STG.128.
// ---------------------------------------------------------------------------
__global__ __launch_bounds__(256, 3) void gather_kernel(
    const float* __restrict__ pred, const float* __restrict__ R,
    const float* __restrict__ I, const int* __restrict__ target) {
  extern __shared__ float stage[];  // [2][16 * RSTRIDE]
  __shared__ int tgt_s[NT];
  __shared__ float rS[NY];
  __shared__ unsigned mask_s[4];    // 128-bit mask over 16B chunks

  const int b   = blockIdx.x >> 1;
  const int arr = blockIdx.x & 1;
  const int tid = threadIdx.x;
  float* g_G = (float*)g_G4;

  // L2 cache policies (sm_80+): streaming input = evict_first,
  // scratch G output = evict_last (pin in L2 for the consumer kernel).
  uint64_t pol_stream, pol_keep;
  asm("createpolicy.fractional.L2::evict_first.b64 %0, 1.0;" : "=l"(pol_stream));
  asm("createpolicy.fractional.L2::evict_last.b64 %0, 1.0;"  : "=l"(pol_keep));

  if (tid < 4) mask_s[tid] = 0u;
  if (tid < NT) tgt_s[tid] = target[b * NT + tid];
  if (tid < NY) {
    const int base = (b * NY + tid) * 3;
    rS[tid] = arr ? ((tid == NY - 1) ? 1.0f : R[base + 1]) : R[base];
  }
  __syncthreads();
  if (tid < NT - 1) {  // only t=0..126 are gathered
    const int cbit = tgt_s[tid] >> 2;
    atomicOr(&mask_s[cbit >> 5], 1u << (cbit & 31));
  }
  __syncthreads();

  const int cc = tid & 127;  // 16B chunk index
  const unsigned on = (mask_s[cc >> 5] >> (cc & 31)) & 1u;
  const int rbase = tid >> 7;  // 0 or 1
  const float* __restrict__ src_arr = arr ? I : pred;

  auto issue = [&](int g) {
    const int r0 = g * 16;
    const float* src = src_arr + ((size_t)b * NY + r0) * C_ + cc * 4;
    float* buf = stage + (g & 1) * (16 * RSTRIDE) + cc * 4;
#pragma unroll
    for (int p = 0; p < 8; ++p) {
      const int r = rbase + 2 * p;
      unsigned sa = (unsigned)__cvta_generic_to_shared(buf + r * RSTRIDE);
      const float* gp = src + (size_t)r * C_;
      asm volatile(
          "{ .reg .pred p0; setp.ne.u32 p0, %0, 0;"
          " @p0 cp.async.cg.shared.global.L2::cache_hint [%1], [%2], 16, %3; }"
          :: "r"(on), "r"(sa), "l"(gp), "l"(pol_stream) : "memory");
    }
    asm volatile("cp.async.commit_group;" ::: "memory");
  };

  issue(0);
  issue(1);

  auto store_keep = [&](float* addr, float4 v) {
    asm volatile(
        "st.global.L2::cache_hint.v4.f32 [%0], {%1, %2, %3, %4}, %5;"
        :: "l"(addr), "f"(v.x), "f"(v.y), "f"(v.z), "f"(v.w), "l"(pol_keep)
        : "memory");
  };

  // Epilogue mapping: jq = quad within 16-row group (0..3), tq = t base.
  const int jq = tid & 3;
  const int tq = tid >> 2;  // 0..63; t = tq + 64*p
  const int tt0 = (tq < NT - 1) ? tgt_s[tq] : 0;
  const int tt1 = (tq + 64 < NT - 1) ? tgt_s[tq + 64] : 0;

  for (int g = 0; g < 8; ++g) {
    if (g == 7) asm volatile("cp.async.wait_group 0;" ::: "memory");
    else        asm volatile("cp.async.wait_group 1;" ::: "memory");
    __syncthreads();

    const int r0 = g * 16;
    const float s0 = rS[r0 + jq * 4 + 0];
    const float s1 = rS[r0 + jq * 4 + 1];
    const float s2 = rS[r0 + jq * 4 + 2];
    const float s3 = rS[r0 + jq * 4 + 3];
    const float* buf = stage + (g & 1) * (16 * RSTRIDE) + (jq * 4) * RSTRIDE;

    {  // t = tq (always < 127 since tq <= 63)
      const float* col = buf + tt0;
      float4 v;
      v.x = col[0 * RSTRIDE] * s0;
      v.y = col[1 * RSTRIDE] * s1;
      v.z = col[2 * RSTRIDE] * s2;
      v.w = col[3 * RSTRIDE] * s3;
      store_keep(&g_G[(((size_t)b * NT + tq) * 2 + arr) * NY + r0 + jq * 4], v);
    }
    if (tq + 64 < NT - 1) {  // t = tq + 64 (skip t = 127)
      const float* col = buf + tt1;
      float4 v;
      v.x = col[0 * RSTRIDE] * s0;
      v.y = col[1 * RSTRIDE] * s1;
      v.z = col[2 * RSTRIDE] * s2;
      v.w = col[3 * RSTRIDE] * s3;
      store_keep(&g_G[(((size_t)b * NT + tq + 64) * 2 + arr) * NY + r0 + jq * 4],
                 v);
    }
    __syncthreads();
    if (g + 2 < 8) issue(g + 2);
  }
}

// ---------------------------------------------------------------------------
// Phase 2 (verbatim R10, regs 31): warp per batch; lane l owns j = 4l..4l+3.
// Affine (A,D) warp scan of x[j] = a[j] + d[j]*x[j-1]. Coefficient rows
// stream through a per-warp cp.async SMEM ring, PF=14. G should now be
// largely L2-resident (evict_last stores + evict_first streaming).
// ---------------------------------------------------------------------------
#define PF 14

__global__ __launch_bounds__(128) void scan_kernel(
    const float* __restrict__ R, const int* __restrict__ target,
    float* __restrict__ out) {
  extern __shared__ float ring[];  // [4 warps][16 slots][256 floats] = 64 KB
  const int l = threadIdx.x & 31;
  const int w = threadIdx.x >> 5;
  const int b = blockIdx.x * 4 + w;
  const unsigned FULL = 0xffffffffu;

  float* wring = ring + w * (16 * 256);
  const float* __restrict__ gG = (const float*)g_G4;
  const size_t gbase = (size_t)b * NT * 256;

  auto issue_row = [&](int r) {
    const float* s1 = gG + gbase + (size_t)r * 256 + l * 4;
    float* d1 = wring + (r & 15) * 256 + l * 4;
    unsigned da = (unsigned)__cvta_generic_to_shared(d1);
    asm volatile(
        "cp.async.cg.shared.global [%0], [%1], 16;\n"
        "cp.async.cg.shared.global [%2], [%3], 16;\n"
        :: "r"(da), "l"(s1), "r"(da + 512), "l"(s1 + 128) : "memory");
    asm volatile("cp.async.commit_group;" ::: "memory");
  };

#pragma unroll
  for (int k = 0; k < PF; ++k) issue_row(k);

  unsigned em[4];
#pragma unroll
  for (int m = 0; m < 4; ++m) {
    const int tg = target[b * NT + l + 32 * m];
    em[m] = __ballot_sync(FULL, tg == EOS_);
  }

  float r2[4];
#pragma unroll
  for (int k = 0; k < 4; ++k)
    r2[k] = R[((size_t)b * NY + 4 * l + k) * 3 + 2];
  const float r2p = __shfl_up_sync(FULL, r2[3], 1);
  const float dsh0 = (l == 0) ? 1.0f : r2p;

  const bool eos0 = em[0] & 1u;
  const float m0v = (l == 0) ? 1.0f : (eos0 ? 1.0f : r2[0]);
  const float m1v = eos0 ? 1.0f : r2[1];
  const float m2v = eos0 ? 1.0f : r2[2];
  const float m3v = eos0 ? 1.0f : r2[3];
  const float P0 = m0v, P1 = P0 * m1v, P2 = P1 * m2v, P3 = P2 * m3v;
  float Pw = P3;
#pragma unroll
  for (int off = 1; off < 32; off <<= 1) {
    const float Po = __shfl_up_sync(FULL, Pw, off);
    if (l >= off) Pw *= Po;
  }
  float pin = __shfl_up_sync(FULL, Pw, 1);
  if (l == 0) pin = 1.0f;
  float row0 = P0 * pin, row1 = P1 * pin, row2 = P2 * pin, row3 = P3 * pin;

  asm volatile("cp.async.wait_group 13;" ::: "memory");  // row 0 ready
  float4 cpc = *(const float4*)(wring + 0 * 256 + l * 4);
  float4 cpi = *(const float4*)(wring + 0 * 256 + 128 + l * 4);

  for (int i = 0; i < NT - 1; ++i) {
    const int rf = i + PF;
    if (rf <= 127) issue_row(rf);
    else asm volatile("cp.async.commit_group;" ::: "memory");

    asm volatile("cp.async.wait_group 13;" ::: "memory");
    const int slot = (i + 1) & 15;
    const float4 npc = *(const float4*)(wring + slot * 256 + l * 4);
    const float4 npi = *(const float4*)(wring + slot * 256 + 128 + l * 4);

    const int ts = i + 1;
    const unsigned ew = (ts & 64) ? ((ts & 32) ? em[3] : em[2])
                                  : ((ts & 32) ? em[1] : em[0]);
    const bool eos = (ew >> (ts & 31)) & 1u;
    const float d0 = eos ? 1.0f : dsh0;
    const float d1 = eos ? 1.0f : r2[0];
    const float d2 = eos ? 1.0f : r2[1];
    const float d3 = eos ? 1.0f : r2[2];

    // a_full[j] = row[j-1]*pC[j-1] + row[j]*pI[j]   (j=0: row[0]*pI[0])
    const float q3 = row3 * cpc.w;
    float qp = __shfl_up_sync(FULL, q3, 1);
    if (l == 0) qp = 0.0f;
    const float a0 = fmaf(row0, cpi.x, qp);
    const float a1 = fmaf(row1, cpi.y, row0 * cpc.x);
    const float a2 = fmaf(row2, cpi.z, row1 * cpc.y);
    const float a3 = fmaf(row3, cpi.w, row2 * cpc.z);

    const float A0 = a0, D0 = d0;
    const float A1 = fmaf(d1, A0, a1), D1 = d1 * D0;
    const float A2 = fmaf(d2, A1, a2), D2 = d2 * D1;
    const float A3 = fmaf(d3, A2, a3), D3 = d3 * D2;

    float As = A3, Ds = D3;
#pragma unroll
    for (int off = 1; off < 32; off <<= 1) {
      const float Ao = __shfl_up_sync(FULL, As, off);
      const float Do = __shfl_up_sync(FULL, Ds, off);
      if (l >= off) { As = fmaf(Ds, Ao, As); Ds *= Do; }
    }
    float xin = __shfl_up_sync(FULL, As, 1);
    if (l == 0) xin = 0.0f;

    row0 = fmaf(D0, xin, A0);
    row1 = fmaf(D1, xin, A1);
    row2 = fmaf(D2, xin, A2);
    row3 = As;

    cpc = npc; cpi = npi;
  }

  if (l == 31) out[b] = row3;
}

// ---------------------------------------------------------------------------
extern "C" void kernel_launch(void* const* d_in, const int* in_sizes, int n_in,
                              void* d_out, int out_size) {
  const float* pred   = (const float*)d_in[0];
  const float* R      = (const float*)d_in[1];
  const float* I      = (const float*)d_in[2];
  const int*   target = (const int*)d_in[3];

  const int smem_g = 2 * 16 * RSTRIDE * (int)sizeof(float);  // 66048 B
  cudaFuncSetAttribute(gather_kernel,
                       cudaFuncAttributeMaxDynamicSharedMemorySize, smem_g);
  const int smem_s = 4 * 16 * 256 * (int)sizeof(float);      // 65536 B
  cudaFuncSetAttribute(scan_kernel,
                       cudaFuncAttributeMaxDynamicSharedMemorySize, smem_s);

  gather_kernel<<<B_ * 2, 256, smem_g>>>(pred, R, I, target);
  scan_kernel<<<B_ / 4, 128, smem_s>>>(R, target, (float*)d_out);
}

// round 17
// speedup vs baseline: 1.2358x; 1.0170x over previous
#include <cuda_runtime.h>
#include <cstdint>
#include <cstddef>

#define B_   1024
#define NT   128
#define NY   128
#define C_   512
#define EOS_ 1

// Compact gathered coefficients: G[b][t][{pC,pI}][j], t slot 127 = pad.
// 128 MiB scratch (device .bss).
__device__ float4 g_G4[(size_t)B_ * NT * 2 * (NY / 4)];

// Padded SMEM row stride (floats): multiple of 4 (16B cp.async), %32==4.
#define RSTRIDE 516

// ---------------------------------------------------------------------------
// Phase 1 (verbatim R10, measured 102.7 us): gather/transpose. CTA = one
// (batch, array) pair: blockIdx.x = b*2 + arr (arr 0 = pred->pC, 1 = I->pI).
// 16-row groups, double-buffered cp.async.cg, skipping 16B chunks no target
// touches. Epilogue: one thread owns (t, j-quad) -> 4 LDS + 1 STG.128.
// ---------------------------------------------------------------------------
__global__ __launch_bounds__(256, 3) void gather_kernel(
    const float* __restrict__ pred, const float* __restrict__ R,
    const float* __restrict__ I, const int* __restrict__ target) {
  extern __shared__ float stage[];  // [2][16 * RSTRIDE]
  __shared__ int tgt_s[NT];
  __shared__ float rS[NY];
  __shared__ unsigned mask_s[4];    // 128-bit mask over 16B chunks

  const int b   = blockIdx.x >> 1;
  const int arr = blockIdx.x & 1;
  const int tid = threadIdx.x;
  float* g_G = (float*)g_G4;

  if (tid < 4) mask_s[tid] = 0u;
  if (tid < NT) tgt_s[tid] = target[b * NT + tid];
  if (tid < NY) {
    const int base = (b * NY + tid) * 3;
    rS[tid] = arr ? ((tid == NY - 1) ? 1.0f : R[base + 1]) : R[base];
  }
  __syncthreads();
  if (tid < NT - 1) {  // only t=0..126 are gathered
    const int cbit = tgt_s[tid] >> 2;
    atomicOr(&mask_s[cbit >> 5], 1u << (cbit & 31));
  }
  __syncthreads();

  const int cc = tid & 127;  // 16B chunk index
  const unsigned on = (mask_s[cc >> 5] >> (cc & 31)) & 1u;
  const int rbase = tid >> 7;  // 0 or 1
  const float* __restrict__ src_arr = arr ? I : pred;

  auto issue = [&](int g) {
    const int r0 = g * 16;
    const float* src = src_arr + ((size_t)b * NY + r0) * C_ + cc * 4;
    float* buf = stage + (g & 1) * (16 * RSTRIDE) + cc * 4;
#pragma unroll
    for (int p = 0; p < 8; ++p) {
      const int r = rbase + 2 * p;
      unsigned sa = (unsigned)__cvta_generic_to_shared(buf + r * RSTRIDE);
      const float* gp = src + (size_t)r * C_;
      asm volatile(
          "{ .reg .pred p0; setp.ne.u32 p0, %0, 0;"
          " @p0 cp.async.cg.shared.global [%1], [%2], 16; }"
          :: "r"(on), "r"(sa), "l"(gp) : "memory");
    }
    asm volatile("cp.async.commit_group;" ::: "memory");
  };

  issue(0);
  issue(1);

  // Epilogue mapping: jq = quad within 16-row group (0..3), tq = t base.
  const int jq = tid & 3;
  const int tq = tid >> 2;  // 0..63; t = tq + 64*p
  const int tt0 = (tq < NT - 1) ? tgt_s[tq] : 0;
  const int tt1 = (tq + 64 < NT - 1) ? tgt_s[tq + 64] : 0;

  for (int g = 0; g < 8; ++g) {
    if (g == 7) asm volatile("cp.async.wait_group 0;" ::: "memory");
    else        asm volatile("cp.async.wait_group 1;" ::: "memory");
    __syncthreads();

    const int r0 = g * 16;
    const float s0 = rS[r0 + jq * 4 + 0];
    const float s1 = rS[r0 + jq * 4 + 1];
    const float s2 = rS[r0 + jq * 4 + 2];
    const float s3 = rS[r0 + jq * 4 + 3];
    const float* buf = stage + (g & 1) * (16 * RSTRIDE) + (jq * 4) * RSTRIDE;

    {  // t = tq (always < 127 since tq <= 63)
      const float* col = buf + tt0;
      float4 v;
      v.x = col[0 * RSTRIDE] * s0;
      v.y = col[1 * RSTRIDE] * s1;
      v.z = col[2 * RSTRIDE] * s2;
      v.w = col[3 * RSTRIDE] * s3;
      *(float4*)&g_G[(((size_t)b * NT + tq) * 2 + arr) * NY + r0 + jq * 4] = v;
    }
    if (tq + 64 < NT - 1) {  // t = tq + 64 (skip t = 127)
      const float* col = buf + tt1;
      float4 v;
      v.x = col[0 * RSTRIDE] * s0;
      v.y = col[1 * RSTRIDE] * s1;
      v.z = col[2 * RSTRIDE] * s2;
      v.w = col[3 * RSTRIDE] * s3;
      *(float4*)&g_G[(((size_t)b * NT + tq + 64) * 2 + arr) * NY + r0 + jq * 4] = v;
    }
    __syncthreads();
    if (g + 2 < 8) issue(g + 2);
  }
}

// ---------------------------------------------------------------------------
// Phase 2: ONE WARP PER CTA (load-balance fix; inner loop verbatim R10).
// blockIdx.x = batch b; lane l owns j = 4l..4l+3. Affine (A,D) warp scan of
// x[j] = a[j] + d[j]*x[j-1]; coefficient rows stream through a per-CTA
// cp.async SMEM ring, PF=14. Grid 1024 x 32 threads -> ~7 uniform CTAs/SM.
// ---------------------------------------------------------------------------
#define PF 14

__global__ __launch_bounds__(32) void scan_kernel(
    const float* __restrict__ R, const int* __restrict__ target,
    float* __restrict__ out) {
  extern __shared__ float wring[];  // [16 slots][256 floats] = 16 KB
  const int l = threadIdx.x;        // lane 0..31
  const int b = blockIdx.x;
  const unsigned FULL = 0xffffffffu;

  const float* __restrict__ gG = (const float*)g_G4;
  const size_t gbase = (size_t)b * NT * 256;

  auto issue_row = [&](int r) {
    const float* s1 = gG + gbase + (size_t)r * 256 + l * 4;
    float* d1 = wring + (r & 15) * 256 + l * 4;
    unsigned da = (unsigned)__cvta_generic_to_shared(d1);
    asm volatile(
        "cp.async.cg.shared.global [%0], [%1], 16;\n"
        "cp.async.cg.shared.global [%2], [%3], 16;\n"
        :: "r"(da), "l"(s1), "r"(da + 512), "l"(s1 + 128) : "memory");
    asm volatile("cp.async.commit_group;" ::: "memory");
  };

#pragma unroll
  for (int k = 0; k < PF; ++k) issue_row(k);

  unsigned em[4];
#pragma unroll
  for (int m = 0; m < 4; ++m) {
    const int tg = target[b * NT + l + 32 * m];
    em[m] = __ballot_sync(FULL, tg == EOS_);
  }

  float r2[4];
#pragma unroll
  for (int k = 0; k < 4; ++k)
    r2[k] = R[((size_t)b * NY + 4 * l + k) * 3 + 2];
  const float r2p = __shfl_up_sync(FULL, r2[3], 1);
  const float dsh0 = (l == 0) ? 1.0f : r2p;

  const bool eos0 = em[0] & 1u;
  const float m0v = (l == 0) ? 1.0f : (eos0 ? 1.0f : r2[0]);
  const float m1v = eos0 ? 1.0f : r2[1];
  const float m2v = eos0 ? 1.0f : r2[2];
  const float m3v = eos0 ? 1.0f : r2[3];
  const float P0 = m0v, P1 = P0 * m1v, P2 = P1 * m2v, P3 = P2 * m3v;
  float Pw = P3;
#pragma unroll
  for (int off = 1; off < 32; off <<= 1) {
    const float Po = __shfl_up_sync(FULL, Pw, off);
    if (l >= off) Pw *= Po;
  }
  float pin = __shfl_up_sync(FULL, Pw, 1);
  if (l == 0) pin = 1.0f;
  float row0 = P0 * pin, row1 = P1 * pin, row2 = P2 * pin, row3 = P3 * pin;

  asm volatile("cp.async.wait_group 13;" ::: "memory");  // row 0 ready
  float4 cpc = *(const float4*)(wring + 0 * 256 + l * 4);
  float4 cpi = *(const float4*)(wring + 0 * 256 + 128 + l * 4);

  for (int i = 0; i < NT - 1; ++i) {
    const int rf = i + PF;
    if (rf <= 127) issue_row(rf);
    else asm volatile("cp.async.commit_group;" ::: "memory");

    asm volatile("cp.async.wait_group 13;" ::: "memory");
    const int slot = (i + 1) & 15;
    const float4 npc = *(const float4*)(wring + slot * 256 + l * 4);
    const float4 npi = *(const float4*)(wring + slot * 256 + 128 + l * 4);

    const int ts = i + 1;
    const unsigned ew = (ts & 64) ? ((ts & 32) ? em[3] : em[2])
                                  : ((ts & 32) ? em[1] : em[0]);
    const bool eos = (ew >> (ts & 31)) & 1u;
    const float d0 = eos ? 1.0f : dsh0;
    const float d1 = eos ? 1.0f : r2[0];
    const float d2 = eos ? 1.0f : r2[1];
    const float d3 = eos ? 1.0f : r2[2];

    // a_full[j] = row[j-1]*pC[j-1] + row[j]*pI[j]   (j=0: row[0]*pI[0])
    const float q3 = row3 * cpc.w;
    float qp = __shfl_up_sync(FULL, q3, 1);
    if (l == 0) qp = 0.0f;
    const float a0 = fmaf(row0, cpi.x, qp);
    const float a1 = fmaf(row1, cpi.y, row0 * cpc.x);
    const float a2 = fmaf(row2, cpi.z, row1 * cpc.y);
    const float a3 = fmaf(row3, cpi.w, row2 * cpc.z);

    const float A0 = a0, D0 = d0;
    const float A1 = fmaf(d1, A0, a1), D1 = d1 * D0;
    const float A2 = fmaf(d2, A1, a2), D2 = d2 * D1;
    const float A3 = fmaf(d3, A2, a3), D3 = d3 * D2;

    float As = A3, Ds = D3;
#pragma unroll
    for (int off = 1; off < 32; off <<= 1) {
      const float Ao = __shfl_up_sync(FULL, As, off);
      const float Do = __shfl_up_sync(FULL, Ds, off);
      if (l >= off) { As = fmaf(Ds, Ao, As); Ds *= Do; }
    }
    float xin = __shfl_up_sync(FULL, As, 1);
    if (l == 0) xin = 0.0f;

    row0 = fmaf(D0, xin, A0);
    row1 = fmaf(D1, xin, A1);
    row2 = fmaf(D2, xin, A2);
    row3 = As;

    cpc = npc; cpi = npi;
  }

  if (l == 31) out[b] = row3;
}

// ---------------------------------------------------------------------------
extern "C" void kernel_launch(void* const* d_in, const int* in_sizes, int n_in,
                              void* d_out, int out_size) {
  const float* pred   = (const float*)d_in[0];
  const float* R      = (const float*)d_in[1];
  const float* I      = (const float*)d_in[2];
  const int*   target = (const int*)d_in[3];

  const int smem_g = 2 * 16 * RSTRIDE * (int)sizeof(float);  // 66048 B
  cudaFuncSetAttribute(gather_kernel,
                       cudaFuncAttributeMaxDynamicSharedMemorySize, smem_g);
  const int smem_s = 16 * 256 * (int)sizeof(float);          // 16384 B
  cudaFuncSetAttribute(scan_kernel,
                       cudaFuncAttributeMaxDynamicSharedMemorySize, smem_s);

  gather_kernel<<<B_ * 2, 256, smem_g>>>(pred, R, I, target);
  scan_kernel<<<B_, 32, smem_s>>>(R, target, (float*)d_out);
}